// round 4
// baseline (speedup 1.0000x reference)
#include <cuda_runtime.h>

// ---------------------------------------------------------------------------
// EfficientAttention, f32x2 packed-FMA version (see R1/R2 notes).
// N=2, D=64, H=W=64, C=64, HEADS=8, hk=hv=8. token t = c*4096 + h*64 + w.
// All staged 64x64 matrices: row stride 64 floats, element e of row r lives at
// float-offset e ^ swk(r), swk(r) = ((r&7)^(r>>3))<<2  -> conflict-free for
// every writer/reader pattern used here (verified per 8-lane phase).
// ---------------------------------------------------------------------------

#define T_TOK 262144
#define PLANE 262144
typedef unsigned long long u64t;

__device__ float g_Q[(size_t)2 * T_TOK * 64];   // 128 MiB scratch
__device__ float g_WT[4 * 4096];                // WqT, WkT, WvT, WrT
__device__ float g_ctxnum[2 * 512];
__device__ float g_den[2 * 64];

#define FMA2(acc, a, b) asm("fma.rn.f32x2 %0, %1, %2, %0;" : "+l"(acc) : "l"(a), "l"(b))

__device__ __forceinline__ float lrelu(float y) { return y >= 0.f ? y : 0.2f * y; }
__device__ __forceinline__ float2 unpk(u64t p) {
    float2 r; asm("mov.b64 {%0, %1}, %2;" : "=f"(r.x), "=f"(r.y) : "l"(p)); return r;
}
__device__ __forceinline__ u64t pk2(float lo, float hi) {
    u64t r; asm("mov.b64 %0, {%1, %2};" : "=l"(r) : "f"(lo), "f"(hi)); return r;
}
__device__ __forceinline__ int swk(int r) { return ((r & 7) ^ (r >> 3)) << 2; }

// setup: transpose the four 64x64 weights into g_WT (contraction-contiguous),
// and zero the tiny global accumulators.
__global__ void setup_kernel(const float* __restrict__ Wq, const float* __restrict__ Wk,
                             const float* __restrict__ Wv, const float* __restrict__ Wr) {
    int t = threadIdx.x, b = blockIdx.x;
    const float* W = (b == 0) ? Wq : (b == 1) ? Wk : (b == 2) ? Wv : Wr;
    float* dst = g_WT + b * 4096;
    for (int idx = t; idx < 4096; idx += 256)
        dst[(idx & 63) * 64 + (idx >> 6)] = W[idx];
    if (b == 0) {
        for (int i = t; i < 2 * 512; i += 256) g_ctxnum[i] = 0.f;
        if (t < 2 * 64) g_den[t] = 0.f;
    }
}

// stage a pre-transposed 64x64 matrix from global into swizzled smem (t in 0..63)
__device__ __forceinline__ void stage_wt(float* __restrict__ Ws,
                                         const float* __restrict__ gw, int t) {
    const float4* g4 = (const float4*)gw;
#pragma unroll
    for (int i = 0; i < 16; i++) {
        float4 v = g4[i * 64 + t];
        int row = i * 4 + (t >> 4);
        int u = t & 15;
        *(float4*)(Ws + row * 64 + ((u << 2) ^ swk(row))) = v;
    }
}

// out[c][e] = sum_d A[c][d]*B[e][d], f32x2-paired along d; 8x8 thread tile.
__device__ __forceinline__ void gemm2(const float* __restrict__ As,
                                      const float* __restrict__ Bs,
                                      int cg, int eg, u64t acc[8][8]) {
    const float* ap[8]; const float* bp[8];
    int ka[8], kb[8];
#pragma unroll
    for (int i = 0; i < 8; i++) {
        ap[i] = As + (cg + i) * 64; ka[i] = swk(cg + i);
        bp[i] = Bs + (eg + i) * 64; kb[i] = swk(eg + i);
        #pragma unroll
        for (int j = 0; j < 8; j++) acc[i][j] = 0ull;
    }
#pragma unroll 4
    for (int p = 0; p < 32; p++) {
        u64t a[8], b[8];
#pragma unroll
        for (int i = 0; i < 8; i++) a[i] = *(const u64t*)(ap[i] + ((p * 2) ^ ka[i]));
#pragma unroll
        for (int j = 0; j < 8; j++) b[j] = *(const u64t*)(bp[j] + ((p * 2) ^ kb[j]));
#pragma unroll
        for (int i = 0; i < 8; i++)
#pragma unroll
            for (int j = 0; j < 8; j++)
                FMA2(acc[i][j], a[i], b[j]);
    }
}

__device__ __forceinline__ void load_sb(const float* s, const float* b, int eg,
                                        float sv8[8], float bv8[8]) {
    float4 s0 = *(const float4*)(s + eg), s1 = *(const float4*)(s + eg + 4);
    float4 b0 = *(const float4*)(b + eg), b1 = *(const float4*)(b + eg + 4);
    sv8[0]=s0.x; sv8[1]=s0.y; sv8[2]=s0.z; sv8[3]=s0.w;
    sv8[4]=s1.x; sv8[5]=s1.y; sv8[6]=s1.z; sv8[7]=s1.w;
    bv8[0]=b0.x; bv8[1]=b0.y; bv8[2]=b0.z; bv8[3]=b0.w;
    bv8[4]=b1.x; bv8[5]=b1.y; bv8[6]=b1.z; bv8[7]=b1.w;
}

__global__ void __launch_bounds__(64) passA_kernel(
    const float* __restrict__ x,
    const float* __restrict__ sk, const float* __restrict__ bk,
    const float* __restrict__ sq, const float* __restrict__ bq,
    const float* __restrict__ sv, const float* __restrict__ bv)
{
    extern __shared__ float sm[];
    float* Xt = sm;            // Xt[c][d] swizzled
    float* W0 = sm + 4096;     // WqT -> later expK[c][e]
    float* W1 = sm + 8192;     // WkT -> later V[c][e]
    float* W2 = sm + 12288;    // WvT
    const int t  = threadIdx.x;
    const int b  = blockIdx.x;
    const int n  = b >> 12;
    const int hw = b & 4095;
    const size_t xbase = (size_t)n * (64ull * PLANE) + (size_t)hw * 64;

    {   // transpose X tile into smem: thread t owns column c=t
        int Kt = swk(t);
#pragma unroll
        for (int u = 0; u < 16; u++) {
            float4 v;
            v.x = x[xbase + (size_t)(u * 4 + 0) * PLANE + t];
            v.y = x[xbase + (size_t)(u * 4 + 1) * PLANE + t];
            v.z = x[xbase + (size_t)(u * 4 + 2) * PLANE + t];
            v.w = x[xbase + (size_t)(u * 4 + 3) * PLANE + t];
            *(float4*)(Xt + t * 64 + ((u << 2) ^ Kt)) = v;
        }
    }
    stage_wt(W0, g_WT,        t);
    stage_wt(W1, g_WT + 4096, t);
    stage_wt(W2, g_WT + 8192, t);
    __syncthreads();

    const int cg = (t & 7) * 8;     // 8 tokens (c)
    const int eg = (t >> 3) * 8;    // 8 channels = one head a = t>>3
    u64t acc[8][8];

    // ---------------- Q: proj + register softmax + store ----------------
    gemm2(Xt, W0, cg, eg, acc);
    {
        float sv8[8], bv8[8];
        load_sb(sq, bq, eg, sv8, bv8);
        const size_t qb = ((size_t)n * T_TOK + hw) * 64 + eg;
#pragma unroll
        for (int i = 0; i < 8; i++) {
            float q[8];
#pragma unroll
            for (int j = 0; j < 8; j++) {
                float2 f = unpk(acc[i][j]);
                q[j] = lrelu((f.x + f.y) * sv8[j] + bv8[j]);
            }
            float m = q[0];
#pragma unroll
            for (int j = 1; j < 8; j++) m = fmaxf(m, q[j]);
            float s = 0.f;
#pragma unroll
            for (int j = 0; j < 8; j++) { q[j] = __expf(q[j] - m); s += q[j]; }
            float inv = 1.f / s;
            float* dst = g_Q + qb + (size_t)(cg + i) * PLANE;
            *(float4*)dst       = make_float4(q[0]*inv, q[1]*inv, q[2]*inv, q[3]*inv);
            *(float4*)(dst + 4) = make_float4(q[4]*inv, q[5]*inv, q[6]*inv, q[7]*inv);
        }
    }
    __syncthreads();   // all threads past Q-GEMM reads of W0

    // ---------------- K: proj -> exp, stash to W0 ----------------
    gemm2(Xt, W1, cg, eg, acc);
    {
        float sv8[8], bv8[8];
        load_sb(sk, bk, eg, sv8, bv8);
#pragma unroll
        for (int i = 0; i < 8; i++) {
            int c = cg + i, Kc = swk(c);
            float e8[8];
#pragma unroll
            for (int j = 0; j < 8; j++) {
                float2 f = unpk(acc[i][j]);
                e8[j] = __expf(lrelu((f.x + f.y) * sv8[j] + bv8[j]));
            }
            *(float4*)(W0 + c * 64 + (eg ^ Kc))       = make_float4(e8[0], e8[1], e8[2], e8[3]);
            *(float4*)(W0 + c * 64 + ((eg + 4) ^ Kc)) = make_float4(e8[4], e8[5], e8[6], e8[7]);
        }
    }
    __syncthreads();   // all threads past K-GEMM reads of W1

    // ---------------- V: proj, stash to W1 ----------------
    gemm2(Xt, W2, cg, eg, acc);
    {
        float sv8[8], bv8[8];
        load_sb(sv, bv, eg, sv8, bv8);
#pragma unroll
        for (int i = 0; i < 8; i++) {
            int c = cg + i, Kc = swk(c);
            float v8[8];
#pragma unroll
            for (int j = 0; j < 8; j++) {
                float2 f = unpk(acc[i][j]);
                v8[j] = lrelu((f.x + f.y) * sv8[j] + bv8[j]);
            }
            *(float4*)(W1 + c * 64 + (eg ^ Kc))       = make_float4(v8[0], v8[1], v8[2], v8[3]);
            *(float4*)(W1 + c * 64 + ((eg + 4) ^ Kc)) = make_float4(v8[4], v8[5], v8[6], v8[7]);
        }
    }
    __syncthreads();

    // ---------------- ctx numerator / denominator ----------------
    {
        const int a2 = t >> 3;              // head
        u64t cacc[4] = {0ull, 0ull, 0ull, 0ull};
        float dsum = 0.f;
#pragma unroll 8
        for (int c = 0; c < 64; c++) {
            int Kc = swk(c);
            float ek = W0[c * 64 + (t ^ Kc)];          // col a2*8+k2 == t
            dsum += ek;
            u64t ek2 = pk2(ek, ek);
            const float* vr = W1 + c * 64;
            FMA2(cacc[0], ek2, *(const u64t*)(vr + ((a2 * 8 + 0) ^ Kc)));
            FMA2(cacc[1], ek2, *(const u64t*)(vr + ((a2 * 8 + 2) ^ Kc)));
            FMA2(cacc[2], ek2, *(const u64t*)(vr + ((a2 * 8 + 4) ^ Kc)));
            FMA2(cacc[3], ek2, *(const u64t*)(vr + ((a2 * 8 + 6) ^ Kc)));
        }
        float* dst = g_ctxnum + n * 512 + t * 8;        // pos = a*64+k*8+v = t*8+v
#pragma unroll
        for (int m = 0; m < 4; m++) {
            float2 f = unpk(cacc[m]);
            atomicAdd(dst + 2 * m,     f.x);
            atomicAdd(dst + 2 * m + 1, f.y);
        }
        atomicAdd(g_den + n * 64 + t, dsum);
    }
}

__global__ void __launch_bounds__(64) passC_kernel(
    const float* __restrict__ x,
    const float* __restrict__ sr, const float* __restrict__ br,
    float* __restrict__ out)
{
    extern __shared__ float sm[];
    float* Qs   = sm;            // Q rows [rv][e] swizzled
    float* Ag   = sm + 4096;     // agg[c][e] swizzled
    float* Ws   = sm + 8192;     // WrT[d][e] swizzled
    float* ctxs = sm + 12288;    // ctx[a][k][v]  (512)
    const int t  = threadIdx.x;
    const int b  = blockIdx.x;
    const int n  = b >> 12;
    const int hw = b & 4095;
    const int h  = hw >> 6, w = hw & 63;

    stage_wt(Ws, g_WT + 3 * 4096, t);
#pragma unroll
    for (int g = t; g < 512; g += 64)
        ctxs[g] = g_ctxnum[n * 512 + g] / g_den[n * 64 + (g >> 3)];
    {   // load Q row rv = t :  global row R = r*32768 + h*512 + w*8 + v
        int r = t >> 3, v = t & 7;
        size_t R = (size_t)r * 32768 + h * 512 + w * 8 + v;
        const float4* src = (const float4*)(g_Q + ((size_t)n * T_TOK + R) * 64);
        int Kt = swk(t);
#pragma unroll
        for (int u = 0; u < 16; u++) {
            float4 val = src[u];
            *(float4*)(Qs + t * 64 + ((u << 2) ^ Kt)) = val;
        }
    }
    __syncthreads();

    const int cg = (t & 7) * 8;
    const int a  = t >> 3;
    const int eg = a * 8;

    // ---- agg[c][a*8+v] = sum_v' ctx[a][c>>3][v'] * Q[(c&7)*8+v][a*8+v'] ----
    {
        u64t c2[4];
#pragma unroll
        for (int m = 0; m < 4; m++)
            c2[m] = *(const u64t*)(ctxs + a * 64 + (t & 7) * 8 + 2 * m);
#pragma unroll
        for (int i = 0; i < 8; i++) {
            float row[8];
#pragma unroll
            for (int v = 0; v < 8; v++) {
                int qr = i * 8 + v, K4 = swk(qr);
                const float* q = Qs + qr * 64;
                u64t acc1 = 0ull;
                FMA2(acc1, c2[0], *(const u64t*)(q + ((eg + 0) ^ K4)));
                FMA2(acc1, c2[1], *(const u64t*)(q + ((eg + 2) ^ K4)));
                FMA2(acc1, c2[2], *(const u64t*)(q + ((eg + 4) ^ K4)));
                FMA2(acc1, c2[3], *(const u64t*)(q + ((eg + 6) ^ K4)));
                float2 f = unpk(acc1);
                row[v] = f.x + f.y;
            }
            int c = cg + i, Kc = swk(c);
            *(float4*)(Ag + c * 64 + (eg ^ Kc))       = make_float4(row[0], row[1], row[2], row[3]);
            *(float4*)(Ag + c * 64 + ((eg + 4) ^ Kc)) = make_float4(row[4], row[5], row[6], row[7]);
        }
    }
    __syncthreads();

    // ---- rep[c][d] = sum_e agg[c][e] * Wr[e][d];  + residual + store ----
    const int dg = (t >> 3) * 8;
    u64t acc[8][8];
    gemm2(Ag, Ws, cg, dg, acc);
    {
        float sv8[8], bv8[8];
        load_sb(sr, br, dg, sv8, bv8);
        const size_t ob = (size_t)n * (64ull * PLANE) + (size_t)hw * 64;
#pragma unroll
        for (int j = 0; j < 8; j++) {
            int d = dg + j;
            const float* xp = x + ob + (size_t)d * PLANE + cg;
            float4 x0 = *(const float4*)xp, x1 = *(const float4*)(xp + 4);
            float4 y0, y1;
            float2 f;
            f = unpk(acc[0][j]); y0.x = lrelu((f.x + f.y) * sv8[j] + bv8[j]) + x0.x;
            f = unpk(acc[1][j]); y0.y = lrelu((f.x + f.y) * sv8[j] + bv8[j]) + x0.y;
            f = unpk(acc[2][j]); y0.z = lrelu((f.x + f.y) * sv8[j] + bv8[j]) + x0.z;
            f = unpk(acc[3][j]); y0.w = lrelu((f.x + f.y) * sv8[j] + bv8[j]) + x0.w;
            f = unpk(acc[4][j]); y1.x = lrelu((f.x + f.y) * sv8[j] + bv8[j]) + x1.x;
            f = unpk(acc[5][j]); y1.y = lrelu((f.x + f.y) * sv8[j] + bv8[j]) + x1.y;
            f = unpk(acc[6][j]); y1.z = lrelu((f.x + f.y) * sv8[j] + bv8[j]) + x1.z;
            f = unpk(acc[7][j]); y1.w = lrelu((f.x + f.y) * sv8[j] + bv8[j]) + x1.w;
            float* op = out + ob + (size_t)d * PLANE + cg;
            *(float4*)op       = y0;
            *(float4*)(op + 4) = y1;
        }
    }
}

extern "C" void kernel_launch(void* const* d_in, const int* in_sizes, int n_in,
                              void* d_out, int out_size) {
    const float* x  = (const float*)d_in[0];
    const float* Wk = (const float*)d_in[1];
    const float* sk = (const float*)d_in[2];
    const float* bk = (const float*)d_in[3];
    const float* Wq = (const float*)d_in[4];
    const float* sq = (const float*)d_in[5];
    const float* bq = (const float*)d_in[6];
    const float* Wv = (const float*)d_in[7];
    const float* sv = (const float*)d_in[8];
    const float* bv = (const float*)d_in[9];
    const float* Wr = (const float*)d_in[10];
    const float* sr = (const float*)d_in[11];
    const float* br = (const float*)d_in[12];
    float* out = (float*)d_out;

    const int smemA = 16384 * 4;   // 65536 B
    const int smemC = 12800 * 4;   // 51200 B
    cudaFuncSetAttribute(passA_kernel, cudaFuncAttributeMaxDynamicSharedMemorySize, smemA);
    cudaFuncSetAttribute(passC_kernel, cudaFuncAttributeMaxDynamicSharedMemorySize, smemC);

    setup_kernel<<<4, 256>>>(Wq, Wk, Wv, Wr);
    passA_kernel<<<8192, 64, smemA>>>(x, sk, bk, sq, bq, sv, bv);
    passC_kernel<<<8192, 64, smemC>>>(x, sr, br, out);
}